// round 2
// baseline (speedup 1.0000x reference)
#include <cuda_runtime.h>

#define BATCH  4
#define LSEQ   4096
#define DMODEL 512
#define NST    64
#define TCH    128
#define QCH    32   // LSEQ / TCH

// ---------------- device scratch (static, allowed) ----------------
__device__ float g_V[TCH * NST];            // v_m = A^m b       [m][n]
__device__ float g_GL[TCH * NST];           // g_t = c A^t       [t][n]
__device__ float g_F2t[TCH * NST];          // F2t[t][n] = v_{127-t}[n]
__device__ float g_G0t[NST * TCH];          // G0t[n][tau] = (c A^{tau+1})[n]
__device__ float g_h[TCH];                  // h[m] = c A^m b
__device__ float g_Mt[NST * NST];           // Mt[m][n] = M[n][m], M = A^128
__device__ float g_P[(size_t)BATCH * QCH * DMODEL * NST];   // [b][q][col][n]
__device__ float g_S[(size_t)BATCH * QCH * DMODEL * NST];   // [b][q][col][n]

// ---------------- precompute: powers of A via log-doubling ----------------
__global__ __launch_bounds__(1024) void precompute_kernel(
    const float* __restrict__ A, const float* __restrict__ Bv,
    const float* __restrict__ Cv)
{
    __shared__ float sA[64 * 64];
    __shared__ float sT[64 * 64];
    int tid = threadIdx.x;

    for (int i = tid; i < 4096; i += 1024) sA[i] = A[i];
    if (tid < 64) { g_V[tid] = Bv[tid]; g_GL[tid] = Cv[tid]; }
    __syncthreads();

    int have = 1;
    for (int k = 0; k < 7; k++) {
        // extend v and g lists: v_{m+have} = A^{have} v_m ; g_{m+have} = g_m A^{have}
        int total = have * 64;
        for (int idx = tid; idx < total; idx += 1024) {
            int m = idx >> 6, n = idx & 63;
            const float* vrow = &g_V[m * 64];
            const float* grow = &g_GL[m * 64];
            float sv = 0.f, sg = 0.f;
            #pragma unroll 8
            for (int j = 0; j < 64; j++) {
                sv += sA[n * 64 + j] * vrow[j];
                sg += grow[j] * sA[j * 64 + n];
            }
            g_V[(m + have) * 64 + n]  = sv;
            g_GL[(m + have) * 64 + n] = sg;
        }
        __syncthreads();
        // square: sT = sA * sA
        for (int idx = tid; idx < 4096; idx += 1024) {
            int i = idx >> 6, j = idx & 63;
            float s = 0.f;
            #pragma unroll 8
            for (int l = 0; l < 64; l++) s += sA[i * 64 + l] * sA[l * 64 + j];
            sT[idx] = s;
        }
        __syncthreads();
        for (int i = tid; i < 4096; i += 1024) sA[i] = sT[i];
        __syncthreads();
        have <<= 1;
    }
    // sA now holds M = A^128

    for (int idx = tid; idx < 4096; idx += 1024) {
        int i = idx >> 6, j = idx & 63;
        g_Mt[j * 64 + i] = sA[idx];
    }
    for (int idx = tid; idx < TCH * NST; idx += 1024) {
        int t = idx >> 6, n = idx & 63;
        g_F2t[t * 64 + n] = g_V[(127 - t) * 64 + n];
    }
    for (int idx = tid; idx < NST * TCH; idx += 1024) {
        int n = idx >> 7, tau = idx & 127;
        float val;
        if (tau < 127) {
            val = g_GL[(tau + 1) * 64 + n];
        } else {  // g_128 = c * M
            float s = 0.f;
            #pragma unroll 8
            for (int j = 0; j < 64; j++) s += g_GL[j] * sA[j * 64 + n];
            val = s;
        }
        g_G0t[n * 128 + tau] = val;
    }
    if (tid < 128) {
        float s = 0.f;
        #pragma unroll 8
        for (int n = 0; n < 64; n++) s += g_GL[n] * g_V[tid * 64 + n];
        g_h[tid] = s;
    }
}

// ---------------- stage A: P[b][q][col][n] = sum_t F2t[t][n] * U[b][qT+t][col] ----------------
__global__ __launch_bounds__(256) void stageA_kernel(const float* __restrict__ U)
{
    int bq = blockIdx.x;
    int b = bq >> 5, q = bq & 31;
    int col0 = blockIdx.y << 6;
    int tid = threadIdx.x;
    int tx = tid & 15, ty = tid >> 4;

    __shared__ float sA[32][64];      // [k][n]  (F2t slice)
    __shared__ float sB[32][64];      // [k][c]  (U slice)
    __shared__ float sT[64][65];      // transpose staging [n][c]

    float acc[4][4] = {};
    const float* Ubase = U + ((size_t)b * LSEQ + (size_t)q * TCH) * DMODEL + col0;

    for (int kk = 0; kk < TCH; kk += 32) {
        #pragma unroll
        for (int p = 0; p < 8; p++) {
            int idx = tid + p * 256;
            int k = idx >> 6, n = idx & 63;
            sA[k][n] = g_F2t[(kk + k) * 64 + n];
            sB[k][n] = Ubase[(size_t)(kk + k) * DMODEL + n];
        }
        __syncthreads();
        #pragma unroll
        for (int k = 0; k < 32; k++) {
            float a[4], bb[4];
            *(float4*)a  = *(const float4*)&sA[k][ty * 4];
            *(float4*)bb = *(const float4*)&sB[k][tx * 4];
            #pragma unroll
            for (int r = 0; r < 4; r++)
                #pragma unroll
                for (int c = 0; c < 4; c++)
                    acc[r][c] += a[r] * bb[c];
        }
        __syncthreads();
    }

    // transpose via smem, then coalesced write of [col][n]
    #pragma unroll
    for (int r = 0; r < 4; r++)
        #pragma unroll
        for (int c = 0; c < 4; c++)
            sT[ty * 4 + r][tx * 4 + c] = acc[r][c];
    __syncthreads();

    float* Pb = g_P + ((size_t)(b * QCH + q) * DMODEL + col0) * NST;
    #pragma unroll
    for (int p = 0; p < 16; p++) {
        int idx = tid + p * 256;
        int c = idx >> 6, n = idx & 63;
        Pb[(size_t)c * NST + n] = sT[n][c];
    }
}

// ---------------- stage B: sequential chunk scan, warp per column ----------------
__global__ __launch_bounds__(256) void stageB_kernel()
{
    __shared__ float sM[NST * NST];  // Mt[m][n]
    int tid = threadIdx.x;
    for (int i = tid; i < NST * NST; i += 256) sM[i] = g_Mt[i];
    __syncthreads();

    int warp = tid >> 5, lane = tid & 31;
    int col = blockIdx.x * 8 + warp;         // 0..2047
    int b = col >> 9, d = col & 511;

    float s0 = 0.f, s1 = 0.f;                // s[lane], s[lane+32]
    for (int q = 0; q < QCH; q++) {
        size_t off = ((size_t)(b * QCH + q) * DMODEL + d) * NST;
        g_S[off + lane]      = s0;           // state entering chunk q
        g_S[off + 32 + lane] = s1;
        float a0 = g_P[off + lane];
        float a1 = g_P[off + 32 + lane];
        #pragma unroll
        for (int mm = 0; mm < 32; mm++) {
            float v = __shfl_sync(0xffffffffu, s0, mm);
            a0 += sM[mm * 64 + lane]      * v;
            a1 += sM[mm * 64 + lane + 32] * v;
        }
        #pragma unroll
        for (int mm = 0; mm < 32; mm++) {
            float v = __shfl_sync(0xffffffffu, s1, mm);
            a0 += sM[(mm + 32) * 64 + lane]      * v;
            a1 += sM[(mm + 32) * 64 + lane + 32] * v;
        }
        s0 = a0; s1 = a1;
    }
}

// ---------------- stage C: Y_chunk = G0 * S + tril-Toeplitz(h) * U_chunk ----------------
__global__ __launch_bounds__(256) void stageC_kernel(const float* __restrict__ U,
                                                     float* __restrict__ Y)
{
    int bq = blockIdx.x;
    int b = bq >> 5, q = bq & 31;
    int col0 = blockIdx.y << 6;
    int tid = threadIdx.x;
    int tx = tid & 15, ty = tid >> 4;

    __shared__ float sA2[32][128];    // [k][tau]
    __shared__ float sB[32][68];      // [k][c], padded
    __shared__ float sh[128];

    if (tid < 128) sh[tid] = g_h[tid];
    __syncthreads();

    float acc[8][4] = {};

    for (int kk = 0; kk < 192; kk += 32) {
        // ---- A tile ----
        if (kk < 64) {
            #pragma unroll
            for (int p = 0; p < 16; p++) {
                int idx = tid + p * 256;
                int k = idx >> 7, t = idx & 127;
                sA2[k][t] = g_G0t[(kk + k) * 128 + t];
            }
        } else {
            int j0 = kk - 64;
            #pragma unroll
            for (int p = 0; p < 16; p++) {
                int idx = tid + p * 256;
                int k = idx >> 7, t = idx & 127;
                int j = j0 + k;
                sA2[k][t] = (t >= j) ? sh[t - j] : 0.f;
            }
        }
        // ---- B tile ----
        if (kk < 64) {
            const float* Sb = g_S + ((size_t)(b * QCH + q) * DMODEL + col0) * NST;
            #pragma unroll
            for (int p = 0; p < 8; p++) {
                int idx = tid + p * 256;
                int c = idx >> 5, j = idx & 31;
                sB[j][c] = Sb[(size_t)c * NST + kk + j];
            }
        } else {
            const float* Ub = U + ((size_t)b * LSEQ + (size_t)q * TCH + (kk - 64)) * DMODEL + col0;
            #pragma unroll
            for (int p = 0; p < 8; p++) {
                int idx = tid + p * 256;
                int k = idx >> 6, c = idx & 63;
                sB[k][c] = Ub[(size_t)k * DMODEL + c];
            }
        }
        __syncthreads();

        #pragma unroll
        for (int k = 0; k < 32; k++) {
            float a[8], bb[4];
            *(float4*)&a[0] = *(const float4*)&sA2[k][ty * 8];
            *(float4*)&a[4] = *(const float4*)&sA2[k][ty * 8 + 4];
            *(float4*)bb    = *(const float4*)&sB[k][tx * 4];
            #pragma unroll
            for (int r = 0; r < 8; r++)
                #pragma unroll
                for (int c = 0; c < 4; c++)
                    acc[r][c] += a[r] * bb[c];
        }
        __syncthreads();
    }

    float* Yb = Y + ((size_t)b * LSEQ + (size_t)q * TCH) * DMODEL + col0;
    #pragma unroll
    for (int r = 0; r < 8; r++) {
        float4 v = make_float4(acc[r][0], acc[r][1], acc[r][2], acc[r][3]);
        *(float4*)&Yb[(size_t)(ty * 8 + r) * DMODEL + tx * 4] = v;
    }
}

// ---------------- launch ----------------
extern "C" void kernel_launch(void* const* d_in, const int* in_sizes, int n_in,
                              void* d_out, int out_size)
{
    const float* u  = (const float*)d_in[0];
    const float* A  = (const float*)d_in[1];
    const float* Bv = (const float*)d_in[2];
    const float* Cv = (const float*)d_in[3];
    float* y = (float*)d_out;

    precompute_kernel<<<1, 1024>>>(A, Bv, Cv);

    dim3 grid(BATCH * QCH, DMODEL / 64);
    stageA_kernel<<<grid, 256>>>(u);
    stageB_kernel<<<256, 256>>>();
    stageC_kernel<<<grid, 256>>>(u, y);
}

// round 4
// speedup vs baseline: 1.2548x; 1.2548x over previous
#include <cuda_runtime.h>

#define BATCH  4
#define LSEQ   4096
#define DMODEL 512
#define NST    64
#define TCH    128
#define QCH    32   // LSEQ / TCH

#define PAD    68   // transpose-staging pad: multiple of 4 (16B-aligned float4 rows),
                    // not a multiple of 32 (conflict-free column access)

// ---------------- device scratch (static, allowed) ----------------
__device__ float  g_V[TCH * NST];            // v_m = A^m b       [m][n]
__device__ float  g_GL[TCH * NST];           // g_t = c A^t       [t][n]
__device__ float  g_F2t[TCH * NST];          // F2t[t][n] = v_{127-t}[n]
__device__ float  g_G0t[NST * TCH];          // G0t[n][tau] = (c A^{tau+1})[n]
__device__ float  g_h[TCH];                  // h[m] = c A^m b
__device__ float2 g_Mpair[NST * 32];         // [mm][lane] = {Mt[mm][lane], Mt[mm][lane+32]}
__device__ float  g_P[(size_t)BATCH * QCH * DMODEL * NST];   // [b][q][col][n]
__device__ float  g_S[(size_t)BATCH * QCH * DMODEL * NST];   // [b][q][col][n]

// ---------------- precompute: powers of A via log-doubling ----------------
// sA  = P = A^(2^k), row-major [i][j]
// sAT = P^T, padded: sAT[j*PAD+i] == sA[i*64+j]   (conflict-free column reads)
__global__ __launch_bounds__(1024) void precompute_kernel(
    const float* __restrict__ A, const float* __restrict__ Bv,
    const float* __restrict__ Cv)
{
    __shared__ float sA[64 * 64];
    __shared__ float sAT[64 * PAD];
    int tid = threadIdx.x;

    for (int idx = tid; idx < 4096; idx += 1024) {
        int i = idx >> 6, j = idx & 63;
        float v = A[idx];
        sA[idx] = v;
        sAT[j * PAD + i] = v;
    }
    if (tid < 64) { g_V[tid] = Bv[tid]; g_GL[tid] = Cv[tid]; }
    __syncthreads();

    int have = 1;
    for (int k = 0; k < 7; k++) {
        // ---- extend: rows [have, 2*have) of V and GL ----
        // v_{m+have}[n] = sum_j P[n][j] v_m[j]   (P[n][j] = sAT[j*PAD+n])
        // g_{m+have}[n] = sum_j g_m[j] P[j][n]   (P[j][n] = sA[j*64+n])
        for (int idx = tid; idx < have * 16; idx += 1024) {
            int m = idx >> 4, n0 = (idx & 15) * 4;
            const float* vrow = &g_V[m * 64];
            const float* grow = &g_GL[m * 64];
            float sv0 = 0.f, sv1 = 0.f, sv2 = 0.f, sv3 = 0.f;
            float sg0 = 0.f, sg1 = 0.f, sg2 = 0.f, sg3 = 0.f;
            #pragma unroll 8
            for (int j = 0; j < 64; j++) {
                float av = vrow[j], ag = grow[j];
                float4 ta = *(const float4*)&sAT[j * PAD + n0];
                float4 tb = *(const float4*)&sA[j * 64 + n0];
                sv0 += av * ta.x; sv1 += av * ta.y; sv2 += av * ta.z; sv3 += av * ta.w;
                sg0 += ag * tb.x; sg1 += ag * tb.y; sg2 += ag * tb.z; sg3 += ag * tb.w;
            }
            *(float4*)&g_V[(m + have) * 64 + n0]  = make_float4(sv0, sv1, sv2, sv3);
            *(float4*)&g_GL[(m + have) * 64 + n0] = make_float4(sg0, sg1, sg2, sg3);
        }

        // ---- squaring: R = P * P, register-tiled 1x4 ----
        int i  = tid >> 4;
        int j0 = (tid & 15) * 4;
        float o0 = 0.f, o1 = 0.f, o2 = 0.f, o3 = 0.f;
        #pragma unroll 8
        for (int l = 0; l < 64; l++) {
            float a = sA[i * 64 + l];
            float4 b4 = *(const float4*)&sA[l * 64 + j0];
            o0 += a * b4.x; o1 += a * b4.y; o2 += a * b4.z; o3 += a * b4.w;
        }
        __syncthreads();              // all reads of sA done (extend + squaring)
        sAT[(j0 + 0) * PAD + i] = o0; // write R^T
        sAT[(j0 + 1) * PAD + i] = o1;
        sAT[(j0 + 2) * PAD + i] = o2;
        sAT[(j0 + 3) * PAD + i] = o3;
        __syncthreads();
        for (int idx = tid; idx < 4096; idx += 1024) {
            int i2 = idx >> 6, j2 = idx & 63;
            sA[idx] = sAT[j2 * PAD + i2];  // R row-major
        }
        __syncthreads();              // sA/sAT consistent; g_V/g_GL visible
        have <<= 1;
    }
    // sA = M = A^128, sAT = M^T (padded)

    // g_Mpair[mm][lane] = {Mt[mm][lane], Mt[mm][lane+32]},  Mt[m][n] = M[n][m] = sAT[m*PAD+n]
    for (int idx = tid; idx < NST * 32; idx += 1024) {
        int mm = idx >> 5, lane = idx & 31;
        g_Mpair[idx] = make_float2(sAT[mm * PAD + lane], sAT[mm * PAD + lane + 32]);
    }
    for (int idx = tid; idx < TCH * NST; idx += 1024) {
        int t = idx >> 6, n = idx & 63;
        g_F2t[t * 64 + n] = g_V[(127 - t) * 64 + n];
    }
    for (int idx = tid; idx < NST * TCH; idx += 1024) {
        int n = idx >> 7, tau = idx & 127;
        float val;
        if (tau < 127) {
            val = g_GL[(tau + 1) * 64 + n];
        } else {  // g_128 = c * M
            float s = 0.f;
            #pragma unroll 8
            for (int j = 0; j < 64; j++) s += g_GL[j] * sA[j * 64 + n];
            val = s;
        }
        g_G0t[n * 128 + tau] = val;
    }
    if (tid < 128) {
        float s = 0.f;
        #pragma unroll 8
        for (int n = 0; n < 64; n++) s += g_GL[n] * g_V[tid * 64 + n];
        g_h[tid] = s;
    }
}

// ---------------- stage A: P[b][q][col][n] = sum_t F2t[t][n] * U[b][qT+t][col] ----------------
__global__ __launch_bounds__(256) void stageA_kernel(const float* __restrict__ U)
{
    int bq = blockIdx.x;
    int b = bq >> 5, q = bq & 31;
    int col0 = blockIdx.y << 6;
    int tid = threadIdx.x;
    int tx = tid & 15, ty = tid >> 4;

    __shared__ float sA[32][64];      // [k][n]  (F2t slice)
    __shared__ float sB[32][64];      // [k][c]  (U slice)
    __shared__ float sT[64][65];      // transpose staging [n][c] (scalar access only)

    float acc[4][4] = {};
    const float* Ubase = U + ((size_t)b * LSEQ + (size_t)q * TCH) * DMODEL + col0;

    for (int kk = 0; kk < TCH; kk += 32) {
        #pragma unroll
        for (int p = 0; p < 8; p++) {
            int idx = tid + p * 256;
            int k = idx >> 6, n = idx & 63;
            sA[k][n] = g_F2t[(kk + k) * 64 + n];
            sB[k][n] = Ubase[(size_t)(kk + k) * DMODEL + n];
        }
        __syncthreads();
        #pragma unroll
        for (int k = 0; k < 32; k++) {
            float a[4], bb[4];
            *(float4*)a  = *(const float4*)&sA[k][ty * 4];
            *(float4*)bb = *(const float4*)&sB[k][tx * 4];
            #pragma unroll
            for (int r = 0; r < 4; r++)
                #pragma unroll
                for (int c = 0; c < 4; c++)
                    acc[r][c] += a[r] * bb[c];
        }
        __syncthreads();
    }

    // transpose via smem, then coalesced write of [col][n]
    #pragma unroll
    for (int r = 0; r < 4; r++)
        #pragma unroll
        for (int c = 0; c < 4; c++)
            sT[ty * 4 + r][tx * 4 + c] = acc[r][c];
    __syncthreads();

    float* Pb = g_P + ((size_t)(b * QCH + q) * DMODEL + col0) * NST;
    #pragma unroll
    for (int p = 0; p < 16; p++) {
        int idx = tid + p * 256;
        int c = idx >> 6, n = idx & 63;
        Pb[(size_t)c * NST + n] = sT[n][c];
    }
}

// ---------------- stage B: sequential chunk scan, warp per column ----------------
__global__ __launch_bounds__(256) void stageB_kernel()
{
    __shared__ float2 sM2[NST * 32];  // [mm][lane] pairs
    int tid = threadIdx.x;
    for (int i = tid; i < NST * 32; i += 256) sM2[i] = g_Mpair[i];
    __syncthreads();

    int warp = tid >> 5, lane = tid & 31;
    int col = blockIdx.x * 8 + warp;         // 0..2047
    int b = col >> 9, d = col & 511;

    float s0 = 0.f, s1 = 0.f;                // s[lane], s[lane+32]
    for (int q = 0; q < QCH; q++) {
        size_t off = ((size_t)(b * QCH + q) * DMODEL + d) * NST;
        g_S[off + lane]      = s0;           // state entering chunk q
        g_S[off + 32 + lane] = s1;
        float p0 = g_P[off + lane];          // issued early; latency hides
        float p1 = g_P[off + 32 + lane];     // behind the shuffle chain
        float a0 = 0.f, a1 = 0.f;
        #pragma unroll
        for (int mm = 0; mm < 32; mm++) {
            float v = __shfl_sync(0xffffffffu, s0, mm);
            float2 m2 = sM2[mm * 32 + lane];
            a0 += m2.x * v;
            a1 += m2.y * v;
        }
        #pragma unroll
        for (int mm = 0; mm < 32; mm++) {
            float v = __shfl_sync(0xffffffffu, s1, mm);
            float2 m2 = sM2[(mm + 32) * 32 + lane];
            a0 += m2.x * v;
            a1 += m2.y * v;
        }
        s0 = a0 + p0; s1 = a1 + p1;
    }
}

// ---------------- stage C: Y_chunk = G0 * S + tril-Toeplitz(h) * U_chunk ----------------
__global__ __launch_bounds__(256) void stageC_kernel(const float* __restrict__ U,
                                                     float* __restrict__ Y)
{
    int bq = blockIdx.x;
    int b = bq >> 5, q = bq & 31;
    int col0 = blockIdx.y << 6;
    int tid = threadIdx.x;
    int tx = tid & 15, ty = tid >> 4;

    __shared__ float sA2[32][128];    // [k][tau]
    __shared__ float sB[32][68];      // [k][c], padded (68 % 4 == 0: float4-safe)
    __shared__ float sh[128];

    if (tid < 128) sh[tid] = g_h[tid];
    __syncthreads();

    float acc[8][4] = {};

    for (int kk = 0; kk < 192; kk += 32) {
        // ---- A tile ----
        if (kk < 64) {
            #pragma unroll
            for (int p = 0; p < 16; p++) {
                int idx = tid + p * 256;
                int k = idx >> 7, t = idx & 127;
                sA2[k][t] = g_G0t[(kk + k) * 128 + t];
            }
        } else {
            int j0 = kk - 64;
            #pragma unroll
            for (int p = 0; p < 16; p++) {
                int idx = tid + p * 256;
                int k = idx >> 7, t = idx & 127;
                int j = j0 + k;
                sA2[k][t] = (t >= j) ? sh[t - j] : 0.f;
            }
        }
        // ---- B tile ----
        if (kk < 64) {
            const float* Sb = g_S + ((size_t)(b * QCH + q) * DMODEL + col0) * NST;
            #pragma unroll
            for (int p = 0; p < 8; p++) {
                int idx = tid + p * 256;
                int c = idx >> 5, j = idx & 31;
                sB[j][c] = Sb[(size_t)c * NST + kk + j];
            }
        } else {
            const float* Ub = U + ((size_t)b * LSEQ + (size_t)q * TCH + (kk - 64)) * DMODEL + col0;
            #pragma unroll
            for (int p = 0; p < 8; p++) {
                int idx = tid + p * 256;
                int k = idx >> 6, c = idx & 63;
                sB[k][c] = Ub[(size_t)k * DMODEL + c];
            }
        }
        __syncthreads();

        #pragma unroll
        for (int k = 0; k < 32; k++) {
            float a[8], bb[4];
            *(float4*)&a[0] = *(const float4*)&sA2[k][ty * 8];
            *(float4*)&a[4] = *(const float4*)&sA2[k][ty * 8 + 4];
            *(float4*)bb    = *(const float4*)&sB[k][tx * 4];
            #pragma unroll
            for (int r = 0; r < 8; r++)
                #pragma unroll
                for (int c = 0; c < 4; c++)
                    acc[r][c] += a[r] * bb[c];
        }
        __syncthreads();
    }

    float* Yb = Y + ((size_t)b * LSEQ + (size_t)q * TCH) * DMODEL + col0;
    #pragma unroll
    for (int r = 0; r < 8; r++) {
        float4 v = make_float4(acc[r][0], acc[r][1], acc[r][2], acc[r][3]);
        *(float4*)&Yb[(size_t)(ty * 8 + r) * DMODEL + tx * 4] = v;
    }
}

// ---------------- launch ----------------
extern "C" void kernel_launch(void* const* d_in, const int* in_sizes, int n_in,
                              void* d_out, int out_size)
{
    const float* u  = (const float*)d_in[0];
    const float* A  = (const float*)d_in[1];
    const float* Bv = (const float*)d_in[2];
    const float* Cv = (const float*)d_in[3];
    float* y = (float*)d_out;

    precompute_kernel<<<1, 1024>>>(A, Bv, Cv);

    dim3 grid(BATCH * QCH, DMODEL / 64);
    stageA_kernel<<<grid, 256>>>(u);
    stageB_kernel<<<256, 256>>>();
    stageC_kernel<<<grid, 256>>>(u, y);
}